// round 4
// baseline (speedup 1.0000x reference)
#include <cuda_runtime.h>

#define N_ 128
#define C_ 64
#define T_ 128
#define V_ 25
#define R_ 8
#define O_ 64
#define P_ (T_*V_)          // 3200 pixels per (n, channel-plane)
#define ALPHA_ 1.0f

#define TT_ 16              // t-tile
#define PP_ (TT_*V_)        // 400 pixels per tile
#define VP_ 28              // v padded to 28 (8B-aligned rows for f32x2)
#define CCH_ 16             // channel chunk for phase A

// Scratch (alloc-free: __device__ globals)
__device__ float g_xm[N_*C_*V_];          // (N,C,V)       0.8 MB
__device__ float g_top[N_*O_*V_*V_];      // (N,O,U,V)    20.5 MB

// ---- packed f32x2 helpers --------------------------------------------------
__device__ __forceinline__ unsigned long long pk2(float x, float y) {
    unsigned long long r;
    asm("mov.b64 %0, {%1, %2};" : "=l"(r) : "f"(x), "f"(y));
    return r;
}
__device__ __forceinline__ void upk2(unsigned long long p, float& x, float& y) {
    asm("mov.b64 {%0, %1}, %2;" : "=f"(x), "=f"(y) : "l"(p));
}
__device__ __forceinline__ void fma2(unsigned long long& d,
                                     unsigned long long a, unsigned long long b) {
    asm("fma.rn.f32x2 %0, %1, %2, %3;" : "=l"(d) : "l"(a), "l"(b), "l"(d));
}

// ---------------------------------------------------------------------------
// K1: xm[n,c,v] = mean_t x[n,c,t,v].  One block per (n,c) row-plane.
// ---------------------------------------------------------------------------
__global__ void k_mean(const float* __restrict__ x) {
    int nc   = blockIdx.x;              // n*C_ + c
    int w    = threadIdx.x >> 5;
    int lane = threadIdx.x & 31;
    const float* base = x + (size_t)nc * (T_*V_);
    float acc = 0.f;
    if (lane < V_) {
        for (int t = w; t < T_; t += 8)
            acc += base[t*V_ + lane];
    }
    __shared__ float s[8][V_];
    if (lane < V_) s[w][lane] = acc;
    __syncthreads();
    if (w == 0 && lane < V_) {
        float r = 0.f;
        #pragma unroll
        for (int i = 0; i < 8; i++) r += s[i][lane];
        g_xm[nc*V_ + lane] = r * (1.0f / T_);
    }
}

// ---------------------------------------------------------------------------
// K2: per n: x1 = w1@xm+b1, x2 = w2@xm+b2, d = tanh(x1[u]-x2[v]),
//            top[o,u,v] = (sum_r w4[o,r] d[r,u,v] + b4[o])*ALPHA + A[u,v]
// ---------------------------------------------------------------------------
__global__ void k_top(const float* __restrict__ A,
                      const float* __restrict__ w1, const float* __restrict__ b1,
                      const float* __restrict__ w2, const float* __restrict__ b2,
                      const float* __restrict__ w4, const float* __restrict__ b4) {
    int n = blockIdx.x;
    __shared__ float xm_s[C_*V_];
    __shared__ float w1_s[R_*C_], w2_s[R_*C_];
    __shared__ float w4_s[O_*R_];
    __shared__ float A_s[V_*V_];
    __shared__ float x1_s[R_*V_], x2_s[R_*V_];
    __shared__ float d_s[R_*V_*V_];
    __shared__ float b1_s[R_], b2_s[R_], b4_s[O_];
    int tid = threadIdx.x;

    for (int i = tid; i < C_*V_; i += 256) xm_s[i] = g_xm[n*C_*V_ + i];
    for (int i = tid; i < R_*C_; i += 256) { w1_s[i] = w1[i]; w2_s[i] = w2[i]; }
    for (int i = tid; i < O_*R_; i += 256) w4_s[i] = w4[i];
    for (int i = tid; i < V_*V_; i += 256) A_s[i] = A[i];
    if (tid < R_) { b1_s[tid] = b1[tid]; b2_s[tid] = b2[tid]; }
    if (tid < O_) b4_s[tid] = b4[tid];
    __syncthreads();

    for (int i = tid; i < 2*R_*V_; i += 256) {
        int which = i / (R_*V_);
        int j = i % (R_*V_);
        int r = j / V_, v = j % V_;
        const float* w = which ? w2_s : w1_s;
        float s = which ? b2_s[r] : b1_s[r];
        #pragma unroll 16
        for (int c = 0; c < C_; c++) s += w[r*C_ + c] * xm_s[c*V_ + v];
        (which ? x2_s : x1_s)[j] = s;
    }
    __syncthreads();

    for (int i = tid; i < R_*V_*V_; i += 256) {
        int r  = i / (V_*V_);
        int uv = i % (V_*V_);
        int u = uv / V_, v = uv % V_;
        d_s[i] = tanhf(x1_s[r*V_ + u] - x2_s[r*V_ + v]);
    }
    __syncthreads();

    float* topn = g_top + (size_t)n * (O_*V_*V_);
    for (int i = tid; i < O_*V_*V_; i += 256) {
        int o  = i / (V_*V_);
        int uv = i % (V_*V_);
        float s = b4_s[o];
        #pragma unroll
        for (int r = 0; r < R_; r++) s += w4_s[o*R_ + r] * d_s[r*V_*V_ + uv];
        topn[i] = s * ALPHA_ + A_s[uv];
    }
}

// ---------------------------------------------------------------------------
// K3 (fused, static smem <= 48KB): block = (n, 16-t tile), 400 threads.
// Phase A: thread owns pixel p; accumulate x3[o=0..63](p) in 32 f32x2 regs,
//          streaming x in 16-channel smem chunks (x read once from HBM).
// Phase B: per 8-o group: spill x3 regs -> smem tile, load top tile,
//          contract over v (f32x2), write out[n,o,t,u] coalesced over u... (u
//          stride-1 in output inner dim).
// Shared: phase A needs 16*400 + 16*64 = 7424 floats; phase B 3584+5000 = 8584.
// One reused region of 8584 floats = 34336 B static.
// ---------------------------------------------------------------------------
#define NT3_ 400
#define SMF_ 8584

__global__ void __launch_bounds__(NT3_, 1)
k_fused(const float* __restrict__ x, const float* __restrict__ w3,
        const float* __restrict__ b3, float* __restrict__ out) {
    __shared__ __align__(16) float sm[SMF_];
    __shared__ float b3s[O_];

    int n   = blockIdx.y;
    int t0  = blockIdx.x * TT_;
    int tid = threadIdx.x;
    if (tid < O_) b3s[tid] = b3[tid];

    // ---- Phase A -----------------------------------------------------------
    float* xc  = sm;            // [CCH_][PP_]  6400 floats
    float* w3c = sm + CCH_*PP_; // [CCH_][O_]   1024 floats

    unsigned long long acc[O_/2];
    #pragma unroll
    for (int k = 0; k < O_/2; k++) acc[k] = 0ull;

    const float* xn = x + (size_t)n * C_ * P_ + (size_t)t0 * V_;
    int p = tid;                               // 0..399

    for (int cc = 0; cc < C_; cc += CCH_) {
        __syncthreads();
        // x chunk: 16 rows x 400 floats as float4 (100 per row)
        for (int i = tid; i < CCH_*PP_/4; i += NT3_) {
            int c = i / (PP_/4), q = i % (PP_/4);
            ((float4*)xc)[i] = *(const float4*)(xn + (size_t)(cc+c)*P_ + q*4);
        }
        // w3 chunk transposed: w3c[c][o] = w3[o*C_ + cc + c]
        for (int i = tid; i < CCH_*O_; i += NT3_) {
            int c = i >> 6, o = i & 63;
            w3c[i] = w3[o*C_ + cc + c];
        }
        __syncthreads();
        #pragma unroll
        for (int c = 0; c < CCH_; c++) {
            float xv = xc[c*PP_ + p];
            unsigned long long xx = pk2(xv, xv);
            const unsigned long long* wrow =
                (const unsigned long long*)&w3c[c*O_];
            #pragma unroll
            for (int k = 0; k < O_/2; k++) fma2(acc[k], xx, wrow[k]);
        }
    }
    __syncthreads();

    // ---- Phase B -----------------------------------------------------------
    float* x3s  = sm;                 // [8][TT_][VP_] 3584 floats
    float* tops = sm + 8*TT_*VP_;     // [8][V_*V_]    5000 floats

    // zero the v-padding lanes once (persist across og iterations)
    if (tid < 8*TT_*3) {
        int o = tid / (TT_*3), r = tid % (TT_*3);
        int t = r / 3, v = V_ + r % 3;
        x3s[(o*TT_ + t)*VP_ + v] = 0.f;
    }

    const float* topn = g_top + (size_t)n * (O_*V_*V_);
    float* outn = out + ((size_t)n * O_) * P_ + (size_t)t0 * V_;

    int tt = p / V_, vv = p % V_;
    int base = tt*VP_ + vv;

    for (int og = 0; og < O_; og += 8) {
        // top tile for this o-group
        for (int i = tid; i < 8*V_*V_; i += NT3_)
            tops[i] = topn[og*V_*V_ + i];
        // spill this o-group's x3 from regs
        {
            int kb = og / 2;
            float a, b;
            #pragma unroll
            for (int j = 0; j < 4; j++) {
                upk2(acc[kb + j], a, b);
                x3s[(2*j  )*TT_*VP_ + base] = a + b3s[og + 2*j];
                x3s[(2*j+1)*TT_*VP_ + base] = b + b3s[og + 2*j + 1];
            }
        }
        __syncthreads();

        // contraction: 400 threads = 200 (o_local,u) units x 2 t-halves
        {
            int unit = tid % 200;
            int half = tid / 200;           // 0 or 1
            int ol = unit / V_;             // 0..7
            int u  = unit % V_;             // 0..24
            unsigned long long tr[VP_/2];
            {
                const float* trow = &tops[ol*V_*V_ + u*V_];
                float tv[VP_];
                #pragma unroll
                for (int v = 0; v < V_; v++) tv[v] = trow[v];
                tv[25] = tv[26] = tv[27] = 0.f;
                #pragma unroll
                for (int k = 0; k < VP_/2; k++) tr[k] = pk2(tv[2*k], tv[2*k+1]);
            }
            const float* xrow0 = &x3s[ol*TT_*VP_ + half*8*VP_];
            float* op = outn + (size_t)(og + ol) * P_ + (half*8)*V_ + u;
            #pragma unroll
            for (int t = 0; t < 8; t++) {
                const unsigned long long* xr =
                    (const unsigned long long*)(xrow0 + t*VP_);
                unsigned long long a2 = 0ull;
                #pragma unroll
                for (int k = 0; k < VP_/2; k++) fma2(a2, tr[k], xr[k]);
                float a, b;
                upk2(a2, a, b);
                op[t*V_] = a + b;
            }
        }
        __syncthreads();   // before next og overwrites x3s/tops
    }
}

// ---------------------------------------------------------------------------
extern "C" void kernel_launch(void* const* d_in, const int* in_sizes, int n_in,
                              void* d_out, int out_size) {
    const float* x  = (const float*)d_in[0];
    const float* A  = (const float*)d_in[1];
    const float* w1 = (const float*)d_in[2];
    const float* b1 = (const float*)d_in[3];
    const float* w2 = (const float*)d_in[4];
    const float* b2 = (const float*)d_in[5];
    const float* w3 = (const float*)d_in[6];
    const float* b3 = (const float*)d_in[7];
    const float* w4 = (const float*)d_in[8];
    const float* b4 = (const float*)d_in[9];
    float* out = (float*)d_out;

    k_mean<<<N_*C_, 256>>>(x);
    k_top<<<N_, 256>>>(A, w1, b1, w2, b2, w4, b4);
    k_fused<<<dim3(T_/TT_, N_), NT3_>>>(x, w3, b3, out);
}